// round 15
// baseline (speedup 1.0000x reference)
#include <cuda_runtime.h>
#include <cuda_fp16.h>
#include <math.h>
#include <stdint.h>

#define SS 2048
#define RR 512
#define NT 256

__device__ float g_of[SS * 64];   // attention output per (s, head*8+c)

__device__ __forceinline__ uint32_t packh2(float lo, float hi) {
    __half2 h = __floats2half2_rn(lo, hi);
    return *(uint32_t*)&h;
}
__device__ __forceinline__ float2 h2f2(uint32_t u) {
    return __half22float2(*(__half2*)&u);
}
__device__ __forceinline__ float tanh_fast(float x) {
    float y; asm("tanh.approx.f32 %0, %1;" : "=f"(y) : "f"(x)); return y;
}
__device__ __forceinline__ void mma_f16(float c[4], const uint32_t a[4],
                                        uint32_t b0, uint32_t b1)
{
    asm("mma.sync.aligned.m16n8k16.row.col.f32.f16.f16.f32 "
        "{%0,%1,%2,%3}, {%4,%5,%6,%7}, {%8,%9}, {%0,%1,%2,%3};"
        : "+f"(c[0]), "+f"(c[1]), "+f"(c[2]), "+f"(c[3])
        : "r"(a[0]), "r"(a[1]), "r"(a[2]), "r"(a[3]), "r"(b0), "r"(b1));
}

// ============================ Kernel A: pool + q + k/v + attention -> OF ============================
// smem layout (words)
static constexpr int A_KV   = 0;                 // 512 rows * 12: K(4xh2)@0-3, V(4xh2)@4-7, pad
static constexpr int A_BIAS = A_KV + RR * 12;    // 512
static constexpr int A_PART = A_BIAS + 512;      // 512
static constexpr int A_POOL = A_PART + 512;      // 64
static constexpr int A_QH   = A_POOL + 64;       // 64
static constexpr int A_MS   = A_QH + 64;         // 4
static constexpr int A_WORDS = A_MS + 4;         // 7300
static constexpr int A_BYTES = A_WORDS * 4;      // 29200 B

__global__ void __launch_bounds__(NT, 2) ga_kernel_a(
    const float* __restrict__ m, const float* __restrict__ mask,
    const float* __restrict__ Wq, const float* __restrict__ Wk,
    const float* __restrict__ Wv)
{
    extern __shared__ float sm[];
    uint32_t* smu = (uint32_t*)sm;
    const int s    = blockIdx.x;
    const int tid  = threadIdx.x;
    const int warp = tid >> 5, lane = tid & 31;
    const int qrow = lane >> 2, qcol = lane & 3;
    const float* m_s    = m + (size_t)s * (RR * 64);
    const float* mask_g = mask + (size_t)s * RR;
    const int r0 = warp * 64;   // warp owns 64 rows; warp = head

    // ---------- bias, ms ----------
    #pragma unroll
    for (int i = tid; i < RR; i += NT)
        sm[A_BIAS + i] = 1e9f * (__ldg(mask_g + i) - 1.0f);
    if (warp == 0) {
        float ms = 0.f;
        #pragma unroll
        for (int j = 0; j < 16; ++j) ms += __ldg(mask_g + lane + 32 * j);
        #pragma unroll
        for (int o = 16; o; o >>= 1) ms += __shfl_xor_sync(0xFFFFFFFFu, ms, o);
        if (lane == 0) sm[A_MS] = ms;
    }

    // ---------- m via float4 LDG.128 (pi frag order) -> Af; pool partials; k/v mma ----------
    uint32_t Af[4][4][4];
    {
        float mk0[4], mk1[4];
        #pragma unroll
        for (int mt = 0; mt < 4; ++mt) {
            mk0[mt] = __ldg(mask_g + r0 + mt * 16 + qrow);
            mk1[mt] = __ldg(mask_g + r0 + mt * 16 + qrow + 8);
        }
        float2 pc[4][2];
        #pragma unroll
        for (int k = 0; k < 4; ++k) { pc[k][0] = make_float2(0.f, 0.f); pc[k][1] = make_float2(0.f, 0.f); }

        #pragma unroll
        for (int ktg = 0; ktg < 4; ++ktg)
            #pragma unroll
            for (int mt = 0; mt < 4; ++mt) {
                const float* base = m_s + (r0 + mt * 16 + qrow) * 64 + ktg * 16 + 4 * qcol;
                float4 f0 = *(const float4*)base;
                float4 f1 = *(const float4*)(base + 8 * 64);
                Af[mt][ktg][0] = packh2(f0.x, f0.y);
                Af[mt][ktg][2] = packh2(f0.z, f0.w);
                Af[mt][ktg][1] = packh2(f1.x, f1.y);
                Af[mt][ktg][3] = packh2(f1.z, f1.w);
                pc[ktg][0].x += f0.x * mk0[mt] + f1.x * mk1[mt];
                pc[ktg][0].y += f0.y * mk0[mt] + f1.y * mk1[mt];
                pc[ktg][1].x += f0.z * mk0[mt] + f1.z * mk1[mt];
                pc[ktg][1].y += f0.w * mk0[mt] + f1.w * mk1[mt];
            }
        #pragma unroll
        for (int k = 0; k < 4; ++k)
            #pragma unroll
            for (int p = 0; p < 2; ++p) {
                #pragma unroll
                for (int o = 4; o <= 16; o <<= 1) {
                    pc[k][p].x += __shfl_xor_sync(0xFFFFFFFFu, pc[k][p].x, o);
                    pc[k][p].y += __shfl_xor_sync(0xFFFFFFFFu, pc[k][p].y, o);
                }
            }
        if (lane < 4) {
            #pragma unroll
            for (int k = 0; k < 4; ++k) {
                float4 pp; pp.x = pc[k][0].x; pp.y = pc[k][0].y; pp.z = pc[k][1].x; pp.w = pc[k][1].y;
                *(float4*)&sm[A_PART + warp * 64 + k * 16 + 4 * lane] = pp;
            }
        }

        // K projection (pi-packed B-frags via __ldg)
        {
            uint32_t bf[4][2];
            #pragma unroll
            for (int ktg = 0; ktg < 4; ++ktg) {
                int d0 = ktg * 16 + 4 * qcol;
                bf[ktg][0] = packh2(__ldg(Wk + d0 * 8 + qrow),       __ldg(Wk + (d0 + 1) * 8 + qrow));
                bf[ktg][1] = packh2(__ldg(Wk + (d0 + 2) * 8 + qrow), __ldg(Wk + (d0 + 3) * 8 + qrow));
            }
            float cc[4][4] = {{0,0,0,0},{0,0,0,0},{0,0,0,0},{0,0,0,0}};
            #pragma unroll
            for (int ktg = 0; ktg < 4; ++ktg)
                #pragma unroll
                for (int mt = 0; mt < 4; ++mt)
                    mma_f16(cc[mt], Af[mt][ktg], bf[ktg][0], bf[ktg][1]);
            #pragma unroll
            for (int mt = 0; mt < 4; ++mt) {
                int row = r0 + mt * 16 + qrow;
                smu[A_KV + row * 12 + qcol]       = packh2(cc[mt][0], cc[mt][1]);
                smu[A_KV + (row + 8) * 12 + qcol] = packh2(cc[mt][2], cc[mt][3]);
            }
        }
        // V projection
        {
            uint32_t bf[4][2];
            #pragma unroll
            for (int ktg = 0; ktg < 4; ++ktg) {
                int d0 = ktg * 16 + 4 * qcol;
                bf[ktg][0] = packh2(__ldg(Wv + d0 * 8 + qrow),       __ldg(Wv + (d0 + 1) * 8 + qrow));
                bf[ktg][1] = packh2(__ldg(Wv + (d0 + 2) * 8 + qrow), __ldg(Wv + (d0 + 3) * 8 + qrow));
            }
            float cc[4][4] = {{0,0,0,0},{0,0,0,0},{0,0,0,0},{0,0,0,0}};
            #pragma unroll
            for (int ktg = 0; ktg < 4; ++ktg)
                #pragma unroll
                for (int mt = 0; mt < 4; ++mt)
                    mma_f16(cc[mt], Af[mt][ktg], bf[ktg][0], bf[ktg][1]);
            #pragma unroll
            for (int mt = 0; mt < 4; ++mt) {
                int row = r0 + mt * 16 + qrow;
                smu[A_KV + row * 12 + 4 + qcol]       = packh2(cc[mt][0], cc[mt][1]);
                smu[A_KV + (row + 8) * 12 + 4 + qcol] = packh2(cc[mt][2], cc[mt][3]);
            }
        }
    }
    __syncthreads();   // KV, PART, bias, ms ready

    // ---------- per-warp pool + q ----------
    float qv[8];
    {
        float p0 = 0.f, p1 = 0.f;
        #pragma unroll
        for (int w = 0; w < 8; ++w) {
            p0 += sm[A_PART + w * 64 + lane];
            p1 += sm[A_PART + w * 64 + lane + 32];
        }
        sm[A_POOL + lane]      = p0;
        sm[A_POOL + lane + 32] = p1;
        float ms = sm[A_MS];
        __syncwarp();
        const int c = lane & 7, qr = lane >> 3;
        float acc = 0.f;
        #pragma unroll
        for (int dd = 0; dd < 16; ++dd) {
            int d = qr * 16 + dd;
            acc += sm[A_POOL + d] * __ldg(&Wq[d * 64 + warp * 8 + c]);
        }
        acc += __shfl_xor_sync(0xFFFFFFFFu, acc, 8);
        acc += __shfl_xor_sync(0xFFFFFFFFu, acc, 16);
        float qs = 0.35355339059327373f / (ms + 1e-10f);
        if (lane < 8) sm[A_QH + warp * 8 + lane] = acc * qs;
        __syncwarp();
        #pragma unroll
        for (int cc = 0; cc < 8; ++cc) qv[cc] = sm[A_QH + warp * 8 + cc];
    }

    // ---------- attention (warp = head); write OF to global ----------
    {
        const uint4* kvp = (const uint4*)(smu + A_KV);
        float sum = 0.f;
        float oa[8] = {0,0,0,0,0,0,0,0};
        #pragma unroll
        for (int i = 0; i < 16; ++i) {
            int r = i * 32 + lane;
            uint4 kw = kvp[r * 3];
            uint4 vw = kvp[r * 3 + 1];
            float bias = sm[A_BIAS + r];
            float2 k0 = h2f2(kw.x), k1 = h2f2(kw.y), k2 = h2f2(kw.z), k3 = h2f2(kw.w);
            float a = qv[0]*k0.x + qv[1]*k0.y + qv[2]*k1.x + qv[3]*k1.y
                    + qv[4]*k2.x + qv[5]*k2.y + qv[6]*k3.x + qv[7]*k3.y + bias;
            float p = __expf(a);
            sum += p;
            float2 v0 = h2f2(vw.x), v1 = h2f2(vw.y), v2 = h2f2(vw.z), v3 = h2f2(vw.w);
            oa[0] += p * v0.x; oa[1] += p * v0.y; oa[2] += p * v1.x; oa[3] += p * v1.y;
            oa[4] += p * v2.x; oa[5] += p * v2.y; oa[6] += p * v3.x; oa[7] += p * v3.y;
        }
        #pragma unroll
        for (int o = 16; o; o >>= 1) sum += __shfl_xor_sync(0xFFFFFFFFu, sum, o);
        #pragma unroll
        for (int c = 0; c < 8; ++c) {
            #pragma unroll
            for (int o = 16; o; o >>= 1) oa[c] += __shfl_xor_sync(0xFFFFFFFFu, oa[c], o);
        }
        if (lane == 0) {
            float inv = 1.f / sum;
            #pragma unroll
            for (int c = 0; c < 8; ++c) g_of[s * 64 + warp * 8 + c] = oa[c] * inv;
        }
    }
}

// ============================ Kernel B: gate + output GEMM ============================
// smem layout (words)
static constexpr int B_WGF = 0;       // Wg B-frags (pi-packed) 2048
static constexpr int B_WOF = 2048;    // Wo B-frags (std-packed) 2048
static constexpr int B_OF  = 4096;    // 64
static constexpr int B_BG  = 4160;    // 64
static constexpr int B_BO  = 4224;    // 64
static constexpr int B_WORDS = 4288;
static constexpr int B_BYTES = B_WORDS * 4;  // 17152 B

__global__ void __launch_bounds__(NT, 2) ga_kernel_b(
    const float* __restrict__ m, const float* __restrict__ Wg,
    const float* __restrict__ bg, const float* __restrict__ Wo,
    const float* __restrict__ bo, float* __restrict__ out)
{
    extern __shared__ float sm[];
    uint32_t* smu = (uint32_t*)sm;
    const int s    = blockIdx.x;
    const int tid  = threadIdx.x;
    const int warp = tid >> 5, lane = tid & 31;
    const int qrow = lane >> 2, qcol = lane & 3;
    const float* m_s = m + (size_t)s * (RR * 64);
    const int r0 = warp * 64;

    // ---------- stage Wg (pi-packed) / Wo (std-packed) frags, OF, bg, bo ----------
    {
        #pragma unroll
        for (int it = 0; it < 4; ++it) {
            int idx = it * 8 + warp;          // 0..31 -> (nt, ktg)
            int nt = idx >> 2, ktg = idx & 3;
            int cc = nt * 8 + qrow;
            int off = ((nt * 4 + ktg) * 32 + lane) * 2;
            int d0g = ktg * 16 + 4 * qcol;    // pi-packed
            smu[B_WGF + off]     = packh2(Wg[d0g * 64 + cc],       Wg[(d0g + 1) * 64 + cc]);
            smu[B_WGF + off + 1] = packh2(Wg[(d0g + 2) * 64 + cc], Wg[(d0g + 3) * 64 + cc]);
            int d0o = ktg * 16 + 2 * qcol;    // standard-packed
            smu[B_WOF + off]     = packh2(Wo[d0o * 64 + cc],       Wo[(d0o + 1) * 64 + cc]);
            smu[B_WOF + off + 1] = packh2(Wo[(d0o + 8) * 64 + cc], Wo[(d0o + 9) * 64 + cc]);
        }
        if (tid < 64) {
            sm[B_OF + tid] = g_of[s * 64 + tid];
            sm[B_BG + tid] = bg[tid];
            sm[B_BO + tid] = bo[tid];
        }
    }
    __syncthreads();

    // ---------- gate (pi-frags from gmem) + output GEMM; h register-resident ----------
    float* outs = out + (size_t)s * (RR * 64);
    #pragma unroll
    for (int mh = 0; mh < 2; ++mh) {
        // load Am half via float4 pi loads from gmem
        uint32_t Am[2][4][4];
        #pragma unroll
        for (int mt2 = 0; mt2 < 2; ++mt2)
            #pragma unroll
            for (int ktg = 0; ktg < 4; ++ktg) {
                const float* base = m_s + (r0 + (mh * 2 + mt2) * 16 + qrow) * 64 + ktg * 16 + 4 * qcol;
                float4 f0 = *(const float4*)base;
                float4 f1 = *(const float4*)(base + 8 * 64);
                Am[mt2][ktg][0] = packh2(f0.x, f0.y);
                Am[mt2][ktg][2] = packh2(f0.z, f0.w);
                Am[mt2][ktg][1] = packh2(f1.x, f1.y);
                Am[mt2][ktg][3] = packh2(f1.z, f1.w);
            }

        uint32_t Ah[2][4][4];
        #pragma unroll
        for (int kh = 0; kh < 4; ++kh) {
            #pragma unroll
            for (int sub = 0; sub < 2; ++sub) {
                const int nt = 2 * kh + sub;
                float cg[2][4] = {{0,0,0,0},{0,0,0,0}};
                #pragma unroll
                for (int ktg = 0; ktg < 4; ++ktg) {
                    uint32_t b0 = smu[B_WGF + ((nt * 4 + ktg) * 32 + lane) * 2];
                    uint32_t b1 = smu[B_WGF + ((nt * 4 + ktg) * 32 + lane) * 2 + 1];
                    #pragma unroll
                    for (int mt2 = 0; mt2 < 2; ++mt2)
                        mma_f16(cg[mt2], Am[mt2][ktg], b0, b1);
                }
                const int col0 = nt * 8 + 2 * qcol;
                float hof0 = 0.5f * sm[B_OF + col0], hof1 = 0.5f * sm[B_OF + col0 + 1];
                float hbg0 = 0.5f * sm[B_BG + col0], hbg1 = 0.5f * sm[B_BG + col0 + 1];
                #pragma unroll
                for (int mt2 = 0; mt2 < 2; ++mt2) {
                    float h0 = fmaf(hof0, tanh_fast(fmaf(0.5f, cg[mt2][0], hbg0)), hof0);
                    float h1 = fmaf(hof1, tanh_fast(fmaf(0.5f, cg[mt2][1], hbg1)), hof1);
                    float h2 = fmaf(hof0, tanh_fast(fmaf(0.5f, cg[mt2][2], hbg0)), hof0);
                    float h3 = fmaf(hof1, tanh_fast(fmaf(0.5f, cg[mt2][3], hbg1)), hof1);
                    Ah[mt2][kh][sub * 2]     = packh2(h0, h1);
                    Ah[mt2][kh][sub * 2 + 1] = packh2(h2, h3);
                }
            }
        }
        #pragma unroll
        for (int nt = 0; nt < 8; ++nt) {
            float co[2][4] = {{0,0,0,0},{0,0,0,0}};
            #pragma unroll
            for (int kh = 0; kh < 4; ++kh) {
                uint32_t b0 = smu[B_WOF + ((nt * 4 + kh) * 32 + lane) * 2];
                uint32_t b1 = smu[B_WOF + ((nt * 4 + kh) * 32 + lane) * 2 + 1];
                #pragma unroll
                for (int mt2 = 0; mt2 < 2; ++mt2)
                    mma_f16(co[mt2], Ah[mt2][kh], b0, b1);
            }
            const int col0 = nt * 8 + 2 * qcol;
            float bo0 = sm[B_BO + col0], bo1 = sm[B_BO + col0 + 1];
            #pragma unroll
            for (int mt2 = 0; mt2 < 2; ++mt2) {
                int row = r0 + (mh * 2 + mt2) * 16 + qrow;
                *(float2*)&outs[row * 64 + col0]       = make_float2(co[mt2][0] + bo0, co[mt2][1] + bo1);
                *(float2*)&outs[(row + 8) * 64 + col0] = make_float2(co[mt2][2] + bo0, co[mt2][3] + bo1);
            }
        }
    }
}

extern "C" void kernel_launch(void* const* d_in, const int* in_sizes, int n_in,
                              void* d_out, int out_size) {
    (void)in_sizes; (void)n_in; (void)out_size;
    const float* m    = (const float*)d_in[0];
    const float* mask = (const float*)d_in[1];
    const float* Wq   = (const float*)d_in[2];
    const float* Wk   = (const float*)d_in[3];
    const float* Wv   = (const float*)d_in[4];
    const float* Wg   = (const float*)d_in[5];
    const float* bg   = (const float*)d_in[6];
    const float* Wo   = (const float*)d_in[7];
    const float* bo   = (const float*)d_in[8];
    float* out = (float*)d_out;

    cudaFuncSetAttribute(ga_kernel_a, cudaFuncAttributeMaxDynamicSharedMemorySize, A_BYTES);
    cudaFuncSetAttribute(ga_kernel_b, cudaFuncAttributeMaxDynamicSharedMemorySize, B_BYTES);
    ga_kernel_a<<<SS, NT, A_BYTES>>>(m, mask, Wq, Wk, Wv);
    ga_kernel_b<<<SS, NT, B_BYTES>>>(m, Wg, bg, Wo, bo, out);
}

// round 16
// speedup vs baseline: 1.3470x; 1.3470x over previous
#include <cuda_runtime.h>
#include <cuda_fp16.h>
#include <math.h>
#include <stdint.h>

#define SS 2048
#define RR 512
#define NT 256
#define NB 296   // persistent grid: 2 CTAs x 148 SMs

// ---- shared memory layout (32-bit word offsets) ----
static constexpr int OFF_WGF  = 0;                    // Wg B-frags (pi-packed) 2048
static constexpr int OFF_WOF  = 2048;                 // Wo B-frags (std-packed) 2048
static constexpr int OFF_KV   = 4096;                 // 512 rows * 12 words: K(4xh2)@0-3, V(4xh2)@4-7, pad
static constexpr int OFF_BIAS = OFF_KV + RR * 12;     // 512 softmax bias (flat, conflict-free)
static constexpr int OFF_PART = OFF_BIAS + 512;       // 8 warps * 64
static constexpr int OFF_POOL = OFF_PART + 512;       // 64 (redundant identical writes)
static constexpr int OFF_QH   = OFF_POOL + 64;        // 64
static constexpr int OFF_OF   = OFF_QH + 64;          // 64
static constexpr int OFF_BG   = OFF_OF + 64;
static constexpr int OFF_BO   = OFF_BG + 64;
static constexpr int OFF_MS   = OFF_BO + 64;          // 4
static constexpr int SMEM_WORDS = OFF_MS + 4;         // 11588
static constexpr int SMEM_BYTES = SMEM_WORDS * 4;     // 46352 B -> 2 CTAs/SM

__device__ __forceinline__ uint32_t packh2(float lo, float hi) {
    __half2 h = __floats2half2_rn(lo, hi);
    return *(uint32_t*)&h;
}
__device__ __forceinline__ float2 h2f2(uint32_t u) {
    return __half22float2(*(__half2*)&u);
}
__device__ __forceinline__ float tanh_fast(float x) {
    float y; asm("tanh.approx.f32 %0, %1;" : "=f"(y) : "f"(x)); return y;
}
__device__ __forceinline__ void mma_f16(float c[4], const uint32_t a[4],
                                        uint32_t b0, uint32_t b1)
{
    asm("mma.sync.aligned.m16n8k16.row.col.f32.f16.f16.f32 "
        "{%0,%1,%2,%3}, {%4,%5,%6,%7}, {%8,%9}, {%0,%1,%2,%3};"
        : "+f"(c[0]), "+f"(c[1]), "+f"(c[2]), "+f"(c[3])
        : "r"(a[0]), "r"(a[1]), "r"(a[2]), "r"(a[3]), "r"(b0), "r"(b1));
}

__global__ void __launch_bounds__(NT, 2) ga_kernel(
    const float* __restrict__ m, const float* __restrict__ mask,
    const float* __restrict__ Wq, const float* __restrict__ Wk,
    const float* __restrict__ Wv, const float* __restrict__ Wg,
    const float* __restrict__ bg, const float* __restrict__ Wo,
    const float* __restrict__ bo, float* __restrict__ out)
{
    extern __shared__ float sm[];
    uint32_t* smu = (uint32_t*)sm;
    const int tid  = threadIdx.x;
    const int warp = tid >> 5, lane = tid & 31;
    const int qrow = lane >> 2, qcol = lane & 3;
    const int r0 = warp * 64;   // warp owns 64 rows; warp = head

    // ========== ONE-TIME staging (persists across s iterations) ==========
    // k-permutation pi for Wg/Wk/Wv (matches float4 A-frag loads):
    //   b0 <- k = base + 4*qcol + {0,1};  b1 <- k = base + 4*qcol + {2,3}
    // Wo STANDARD packing (matches gate-accumulator A-frag identity):
    //   b0 <- k = base + 2*qcol + {0,1};  b1 <- k = base + 2*qcol + {8,9}
    // Layout: word = OFF + ((nt*4 + ktg)*32 + lane)*2 + {0,1}  (LDS.64-safe)
    {
        #pragma unroll
        for (int it = 0; it < 4; ++it) {
            int idx = it * 8 + warp;          // 0..31 -> (nt, ktg)
            int nt = idx >> 2, ktg = idx & 3;
            int cc = nt * 8 + qrow;
            int off = ((nt * 4 + ktg) * 32 + lane) * 2;
            int d0g = ktg * 16 + 4 * qcol;    // pi-packed
            smu[OFF_WGF + off]     = packh2(Wg[d0g * 64 + cc],       Wg[(d0g + 1) * 64 + cc]);
            smu[OFF_WGF + off + 1] = packh2(Wg[(d0g + 2) * 64 + cc], Wg[(d0g + 3) * 64 + cc]);
            int d0o = ktg * 16 + 2 * qcol;    // standard-packed
            smu[OFF_WOF + off]     = packh2(Wo[d0o * 64 + cc],       Wo[(d0o + 1) * 64 + cc]);
            smu[OFF_WOF + off + 1] = packh2(Wo[(d0o + 8) * 64 + cc], Wo[(d0o + 9) * 64 + cc]);
        }
        if (tid < 64) { sm[OFF_BG + tid] = bg[tid]; sm[OFF_BO + tid] = bo[tid]; }
        // K/V B-frags (pi-packed) into registers once
    }
    uint32_t bk[4][2], bv[4][2];
    #pragma unroll
    for (int ktg = 0; ktg < 4; ++ktg) {
        int d0 = ktg * 16 + 4 * qcol;
        bk[ktg][0] = packh2(__ldg(Wk + d0 * 8 + qrow),       __ldg(Wk + (d0 + 1) * 8 + qrow));
        bk[ktg][1] = packh2(__ldg(Wk + (d0 + 2) * 8 + qrow), __ldg(Wk + (d0 + 3) * 8 + qrow));
        bv[ktg][0] = packh2(__ldg(Wv + d0 * 8 + qrow),       __ldg(Wv + (d0 + 1) * 8 + qrow));
        bv[ktg][1] = packh2(__ldg(Wv + (d0 + 2) * 8 + qrow), __ldg(Wv + (d0 + 3) * 8 + qrow));
    }

    // ========== persistent loop over sequence rows ==========
    for (int s = blockIdx.x; s < SS; s += gridDim.x) {
        const float* m_s    = m + (size_t)s * (RR * 64);
        const float* mask_g = mask + (size_t)s * RR;

        // ---------- per-s: bias + ms ----------
        #pragma unroll
        for (int i = tid; i < RR; i += NT)
            sm[OFF_BIAS + i] = 1e9f * (__ldg(mask_g + i) - 1.0f);
        if (warp == 0) {
            float ms = 0.f;
            #pragma unroll
            for (int j = 0; j < 16; ++j) ms += __ldg(mask_g + lane + 32 * j);
            #pragma unroll
            for (int o = 16; o; o >>= 1) ms += __shfl_xor_sync(0xFFFFFFFFu, ms, o);
            if (lane == 0) sm[OFF_MS] = ms;
        }

        // ---------- Phase 1: m via float4 LDG.128 (pi frag order) -> Af; pool; k/v mma ----------
        uint32_t Af[4][4][4];
        {
            float mk0[4], mk1[4];
            #pragma unroll
            for (int mt = 0; mt < 4; ++mt) {
                mk0[mt] = __ldg(mask_g + r0 + mt * 16 + qrow);
                mk1[mt] = __ldg(mask_g + r0 + mt * 16 + qrow + 8);
            }
            float2 pc[4][2];
            #pragma unroll
            for (int k = 0; k < 4; ++k) { pc[k][0] = make_float2(0.f, 0.f); pc[k][1] = make_float2(0.f, 0.f); }

            #pragma unroll
            for (int ktg = 0; ktg < 4; ++ktg)
                #pragma unroll
                for (int mt = 0; mt < 4; ++mt) {
                    const float* base = m_s + (r0 + mt * 16 + qrow) * 64 + ktg * 16 + 4 * qcol;
                    float4 f0 = *(const float4*)base;            // (row,   k0..k3)
                    float4 f1 = *(const float4*)(base + 8 * 64); // (row+8, k0..k3)
                    Af[mt][ktg][0] = packh2(f0.x, f0.y);
                    Af[mt][ktg][2] = packh2(f0.z, f0.w);
                    Af[mt][ktg][1] = packh2(f1.x, f1.y);
                    Af[mt][ktg][3] = packh2(f1.z, f1.w);
                    pc[ktg][0].x += f0.x * mk0[mt] + f1.x * mk1[mt];
                    pc[ktg][0].y += f0.y * mk0[mt] + f1.y * mk1[mt];
                    pc[ktg][1].x += f0.z * mk0[mt] + f1.z * mk1[mt];
                    pc[ktg][1].y += f0.w * mk0[mt] + f1.w * mk1[mt];
                }
            // pool partial reduce over qrow (lanes sharing qcol): xor 4, 8, 16
            #pragma unroll
            for (int k = 0; k < 4; ++k)
                #pragma unroll
                for (int p = 0; p < 2; ++p) {
                    #pragma unroll
                    for (int o = 4; o <= 16; o <<= 1) {
                        pc[k][p].x += __shfl_xor_sync(0xFFFFFFFFu, pc[k][p].x, o);
                        pc[k][p].y += __shfl_xor_sync(0xFFFFFFFFu, pc[k][p].y, o);
                    }
                }
            if (lane < 4) {
                #pragma unroll
                for (int k = 0; k < 4; ++k) {
                    float4 pp; pp.x = pc[k][0].x; pp.y = pc[k][0].y; pp.z = pc[k][1].x; pp.w = pc[k][1].y;
                    *(float4*)&sm[OFF_PART + warp * 64 + k * 16 + 4 * lane] = pp;
                }
            }

            // K projection
            {
                float cc[4][4] = {{0,0,0,0},{0,0,0,0},{0,0,0,0},{0,0,0,0}};
                #pragma unroll
                for (int ktg = 0; ktg < 4; ++ktg)
                    #pragma unroll
                    for (int mt = 0; mt < 4; ++mt)
                        mma_f16(cc[mt], Af[mt][ktg], bk[ktg][0], bk[ktg][1]);
                #pragma unroll
                for (int mt = 0; mt < 4; ++mt) {
                    int row = r0 + mt * 16 + qrow;
                    smu[OFF_KV + row * 12 + qcol]       = packh2(cc[mt][0], cc[mt][1]);
                    smu[OFF_KV + (row + 8) * 12 + qcol] = packh2(cc[mt][2], cc[mt][3]);
                }
            }
            // V projection
            {
                float cc[4][4] = {{0,0,0,0},{0,0,0,0},{0,0,0,0},{0,0,0,0}};
                #pragma unroll
                for (int ktg = 0; ktg < 4; ++ktg)
                    #pragma unroll
                    for (int mt = 0; mt < 4; ++mt)
                        mma_f16(cc[mt], Af[mt][ktg], bv[ktg][0], bv[ktg][1]);
                #pragma unroll
                for (int mt = 0; mt < 4; ++mt) {
                    int row = r0 + mt * 16 + qrow;
                    smu[OFF_KV + row * 12 + 4 + qcol]       = packh2(cc[mt][0], cc[mt][1]);
                    smu[OFF_KV + (row + 8) * 12 + 4 + qcol] = packh2(cc[mt][2], cc[mt][3]);
                }
            }
        }
        __syncthreads();   // B2: KV, PART, bias, ms ready (W frags ready since pre-loop)

        // ---------- Phase 2: per-warp pool + q ----------
        float qv[8];
        {
            float p0 = 0.f, p1 = 0.f;
            #pragma unroll
            for (int w = 0; w < 8; ++w) {
                p0 += sm[OFF_PART + w * 64 + lane];
                p1 += sm[OFF_PART + w * 64 + lane + 32];
            }
            sm[OFF_POOL + lane]      = p0;   // all warps write identical values (benign)
            sm[OFF_POOL + lane + 32] = p1;
            float ms = sm[OFF_MS];
            __syncwarp();
            const int c = lane & 7, qr = lane >> 3;
            float acc = 0.f;
            #pragma unroll
            for (int dd = 0; dd < 16; ++dd) {
                int d = qr * 16 + dd;
                acc += sm[OFF_POOL + d] * __ldg(&Wq[d * 64 + warp * 8 + c]);
            }
            acc += __shfl_xor_sync(0xFFFFFFFFu, acc, 8);
            acc += __shfl_xor_sync(0xFFFFFFFFu, acc, 16);
            float qs = 0.35355339059327373f / (ms + 1e-10f);
            if (lane < 8) sm[OFF_QH + warp * 8 + lane] = acc * qs;
            __syncwarp();
            #pragma unroll
            for (int cc = 0; cc < 8; ++cc) qv[cc] = sm[OFF_QH + warp * 8 + cc];
        }

        // ---------- Phase 3: attention (warp = head) with LDS.128 K/V ----------
        {
            const uint4* kvp = (const uint4*)(smu + OFF_KV);   // row = 3 uint4
            float sum = 0.f;
            float oa[8] = {0,0,0,0,0,0,0,0};
            #pragma unroll
            for (int i = 0; i < 16; ++i) {
                int r = i * 32 + lane;
                uint4 kw = kvp[r * 3];
                uint4 vw = kvp[r * 3 + 1];
                float bias = sm[OFF_BIAS + r];
                float2 k0 = h2f2(kw.x), k1 = h2f2(kw.y), k2 = h2f2(kw.z), k3 = h2f2(kw.w);
                float a = qv[0]*k0.x + qv[1]*k0.y + qv[2]*k1.x + qv[3]*k1.y
                        + qv[4]*k2.x + qv[5]*k2.y + qv[6]*k3.x + qv[7]*k3.y + bias;
                float p = __expf(a);
                sum += p;
                float2 v0 = h2f2(vw.x), v1 = h2f2(vw.y), v2 = h2f2(vw.z), v3 = h2f2(vw.w);
                oa[0] += p * v0.x; oa[1] += p * v0.y; oa[2] += p * v1.x; oa[3] += p * v1.y;
                oa[4] += p * v2.x; oa[5] += p * v2.y; oa[6] += p * v3.x; oa[7] += p * v3.y;
            }
            #pragma unroll
            for (int o = 16; o; o >>= 1) sum += __shfl_xor_sync(0xFFFFFFFFu, sum, o);
            #pragma unroll
            for (int c = 0; c < 8; ++c) {
                #pragma unroll
                for (int o = 16; o; o >>= 1) oa[c] += __shfl_xor_sync(0xFFFFFFFFu, oa[c], o);
            }
            if (lane == 0) {
                float inv = 1.f / sum;
                #pragma unroll
                for (int c = 0; c < 8; ++c) sm[OFF_OF + warp * 8 + c] = oa[c] * inv;
            }
        }
        __syncthreads();   // B3: OF ready for all warps

        // ---------- Phase 4: gate (pi-frags) + output GEMM (std identity); h register-resident ----------
        float* outs = out + (size_t)s * (RR * 64);
        #pragma unroll
        for (int mh = 0; mh < 2; ++mh) {
            uint32_t Ah[2][4][4];
            #pragma unroll
            for (int kh = 0; kh < 4; ++kh) {
                #pragma unroll
                for (int sub = 0; sub < 2; ++sub) {
                    const int nt = 2 * kh + sub;
                    float cg[2][4] = {{0,0,0,0},{0,0,0,0}};
                    #pragma unroll
                    for (int ktg = 0; ktg < 4; ++ktg) {
                        uint32_t b0 = smu[OFF_WGF + ((nt * 4 + ktg) * 32 + lane) * 2];
                        uint32_t b1 = smu[OFF_WGF + ((nt * 4 + ktg) * 32 + lane) * 2 + 1];
                        #pragma unroll
                        for (int mt2 = 0; mt2 < 2; ++mt2)
                            mma_f16(cg[mt2], Af[mh * 2 + mt2][ktg], b0, b1);
                    }
                    const int col0 = nt * 8 + 2 * qcol;
                    float hof0 = 0.5f * sm[OFF_OF + col0], hof1 = 0.5f * sm[OFF_OF + col0 + 1];
                    float hbg0 = 0.5f * sm[OFF_BG + col0], hbg1 = 0.5f * sm[OFF_BG + col0 + 1];
                    #pragma unroll
                    for (int mt2 = 0; mt2 < 2; ++mt2) {
                        float h0 = fmaf(hof0, tanh_fast(fmaf(0.5f, cg[mt2][0], hbg0)), hof0);
                        float h1 = fmaf(hof1, tanh_fast(fmaf(0.5f, cg[mt2][1], hbg1)), hof1);
                        float h2 = fmaf(hof0, tanh_fast(fmaf(0.5f, cg[mt2][2], hbg0)), hof0);
                        float h3 = fmaf(hof1, tanh_fast(fmaf(0.5f, cg[mt2][3], hbg1)), hof1);
                        Ah[mt2][kh][sub * 2]     = packh2(h0, h1);
                        Ah[mt2][kh][sub * 2 + 1] = packh2(h2, h3);
                    }
                }
            }
            #pragma unroll
            for (int nt = 0; nt < 8; ++nt) {
                float co[2][4] = {{0,0,0,0},{0,0,0,0}};
                #pragma unroll
                for (int kh = 0; kh < 4; ++kh) {
                    uint32_t b0 = smu[OFF_WOF + ((nt * 4 + kh) * 32 + lane) * 2];
                    uint32_t b1 = smu[OFF_WOF + ((nt * 4 + kh) * 32 + lane) * 2 + 1];
                    #pragma unroll
                    for (int mt2 = 0; mt2 < 2; ++mt2)
                        mma_f16(co[mt2], Ah[mt2][kh], b0, b1);
                }
                const int col0 = nt * 8 + 2 * qcol;
                float bo0 = sm[OFF_BO + col0], bo1 = sm[OFF_BO + col0 + 1];
                #pragma unroll
                for (int mt2 = 0; mt2 < 2; ++mt2) {
                    int row = r0 + (mh * 2 + mt2) * 16 + qrow;
                    *(float2*)&outs[row * 64 + col0]       = make_float2(co[mt2][0] + bo0, co[mt2][1] + bo1);
                    *(float2*)&outs[(row + 8) * 64 + col0] = make_float2(co[mt2][2] + bo0, co[mt2][3] + bo1);
                }
            }
        }
    }   // end persistent s loop
}

extern "C" void kernel_launch(void* const* d_in, const int* in_sizes, int n_in,
                              void* d_out, int out_size) {
    (void)in_sizes; (void)n_in; (void)out_size;
    const float* m    = (const float*)d_in[0];
    const float* mask = (const float*)d_in[1];
    const float* Wq   = (const float*)d_in[2];
    const float* Wk   = (const float*)d_in[3];
    const float* Wv   = (const float*)d_in[4];
    const float* Wg   = (const float*)d_in[5];
    const float* bg   = (const float*)d_in[6];
    const float* Wo   = (const float*)d_in[7];
    const float* bo   = (const float*)d_in[8];
    float* out = (float*)d_out;

    cudaFuncSetAttribute(ga_kernel, cudaFuncAttributeMaxDynamicSharedMemorySize, SMEM_BYTES);
    ga_kernel<<<NB, NT, SMEM_BYTES>>>(m, mask, Wq, Wk, Wv, Wg, bg, Wo, bo, out);
}